// round 15
// baseline (speedup 1.0000x reference)
#include <cuda_runtime.h>
#include <cuda_fp16.h>
#include <math.h>
#include <stdint.h>

// ---------------- problem constants ----------------
#define B_ 2
#define E_ 256
#define NH_ 8
#define NL_ 4
#define NP_ 4
#define DF_ 1024
#define NLAYERS_ 6
#define HD_ 32
#define S_ 10548
#define M_ (B_*S_)          // 21096 query rows

__device__ __constant__ int c_LD[4] = {4, 2, 1, 1};
__device__ __constant__ int c_LH[4] = {48, 24, 12, 6};
__device__ __constant__ int c_LW[4] = {48, 24, 12, 6};

// ---------------- scratch (allocation-free) ----------------
__device__ float  g_x   [M_*E_];    // fp32 residual stream
__device__ __half g_xh  [M_*E_];    // fp16 copy of x (GEMM A)
__device__ float  g_pos [M_*E_];
__device__ __half g_qh  [M_*E_];    // fp16 q = x + pos (GEMM A)
__device__ __half g_valh[M_*E_];    // fp16 value tensor
__device__ __half g_samh[M_*E_];    // fp16 sampler output (GEMM A)
__device__ float  g_oa  [M_*512];   // packed: [0,384) offsets, [384,512) attn logits
__device__ __half g_hidh[M_*DF_];   // fp16 hidden (GEMM A)

// fp16 weights [K,N] row-major
__device__ __half g_Wval[NLAYERS_*E_*E_];
__device__ __half g_Wqa [NLAYERS_*E_*512];
__device__ __half g_Wout[NLAYERS_*E_*E_];
__device__ __half g_Wff1[NLAYERS_*E_*DF_];
__device__ __half g_Wff2[NLAYERS_*DF_*E_];
__device__ float  g_bqa [NLAYERS_*512];

// ---------------- helpers ----------------
__device__ __forceinline__ void mma_f16(float c[4], const unsigned a[4], const unsigned b[2])
{
    asm volatile("mma.sync.aligned.m16n8k16.row.col.f32.f16.f16.f32 "
        "{%0,%1,%2,%3}, {%4,%5,%6,%7}, {%8,%9}, {%0,%1,%2,%3};\n"
        : "+f"(c[0]), "+f"(c[1]), "+f"(c[2]), "+f"(c[3])
        : "r"(a[0]), "r"(a[1]), "r"(a[2]), "r"(a[3]), "r"(b[0]), "r"(b[1]));
}

__device__ __forceinline__ void cp_async16(void* smem, const void* gmem, bool valid)
{
    unsigned saddr = (unsigned)__cvta_generic_to_shared(smem);
    int sz = valid ? 16 : 0;
    asm volatile("cp.async.cg.shared.global [%0], [%1], 16, %2;\n"
                 :: "r"(saddr), "l"(gmem), "r"(sz));
}
__device__ __forceinline__ void cp_commit() { asm volatile("cp.async.commit_group;\n"); }
template<int N> __device__ __forceinline__ void cp_wait() { asm volatile("cp.async.wait_group %0;\n" :: "n"(N)); }

#define LDSM_X4(r0,r1,r2,r3,addr) \
    asm volatile("ldmatrix.sync.aligned.m8n8.x4.shared.b16 {%0,%1,%2,%3}, [%4];\n" \
        : "=r"(r0), "=r"(r1), "=r"(r2), "=r"(r3) : "r"(addr))

#define LDSM_X4T(r0,r1,r2,r3,addr) \
    asm volatile("ldmatrix.sync.aligned.m8n8.x4.trans.shared.b16 {%0,%1,%2,%3}, [%4];\n" \
        : "=r"(r0), "=r"(r1), "=r"(r2), "=r"(r3) : "r"(addr))

__device__ __forceinline__ void store_half4(__half* p, float a, float b, float c, float d)
{
    __half2 h01 = __floats2half2_rn(a, b);
    __half2 h23 = __floats2half2_rn(c, d);
    uint2 u;
    u.x = *reinterpret_cast<unsigned*>(&h01);
    u.y = *reinterpret_cast<unsigned*>(&h23);
    *reinterpret_cast<uint2*>(p) = u;
}

// ---------------- merged weight prep (single launch) ----------------
__global__ void prep_weights(const float* __restrict__ W_val, const float* __restrict__ W_out,
                             const float* __restrict__ W_ff1, const float* __restrict__ W_ff2,
                             const float* __restrict__ W_off, const float* __restrict__ W_attn,
                             const float* __restrict__ b_off, const float* __restrict__ b_attn)
{
    const int nVal = NLAYERS_*E_*E_;
    const int nFf  = NLAYERS_*E_*DF_;
    const int nQa  = NLAYERS_*E_*512;
    int i = blockIdx.x * blockDim.x + threadIdx.x;
    if (i < nVal) { g_Wval[i] = __float2half_rn(W_val[i]); return; }
    i -= nVal;
    if (i < nVal) { g_Wout[i] = __float2half_rn(W_out[i]); return; }
    i -= nVal;
    if (i < nFf)  { g_Wff1[i] = __float2half_rn(W_ff1[i]); return; }
    i -= nFf;
    if (i < nFf)  { g_Wff2[i] = __float2half_rn(W_ff2[i]); return; }
    i -= nFf;
    if (i < nQa) {
        int l = i / (E_ * 512);
        int rem = i - l * E_ * 512;
        int k = rem >> 9;
        int c = rem & 511;
        float v = (c < 384) ? W_off[(size_t)l*E_*384 + k*384 + c]
                            : W_attn[(size_t)l*E_*128 + k*128 + (c - 384)];
        g_Wqa[i] = __float2half_rn(v);
        return;
    }
    i -= nQa;
    if (i < NLAYERS_ * 512) {
        int l = i >> 9;
        int c = i & 511;
        g_bqa[i] = (c < 384) ? b_off[l*384 + c] : b_attn[l*128 + (c - 384)];
    }
}
#define PREP_TOT (2*NLAYERS_*E_*E_ + 2*NLAYERS_*E_*DF_ + NLAYERS_*E_*512 + NLAYERS_*512)

// ---------------- coalesced transposing init (per level) ----------------
__global__ void init_t_kernel(const float* __restrict__ f, const float* __restrict__ p,
                              const float* __restrict__ le_row, int n, int s0)
{
    __shared__ float tf[32][33];
    __shared__ float tp[32][33];
    int i0 = blockIdx.x * 32;
    int e0 = blockIdx.y * 32;
    int b  = blockIdx.z;
    int tx = threadIdx.x, ty = threadIdx.y;

    int ig = i0 + tx;
    int eg = e0 + ty;
    if (ig < n) {
        size_t src = (size_t)(b*E_ + eg) * n + ig;
        tf[ty][tx] = f[src];
        tp[ty][tx] = p[src];
    }
    __syncthreads();

    int iw = i0 + ty;
    int ew = e0 + tx;
    if (iw < n) {
        size_t dst = (size_t)(b*S_ + s0 + iw) * E_ + ew;
        float xv = tf[tx][ty];
        float pv = tp[tx][ty] + le_row[ew];
        g_x[dst]   = xv;
        g_xh[dst]  = __float2half_rn(xv);
        g_pos[dst] = pv;
        g_qh[dst]  = __float2half_rn(xv + pv);
    }
}

// ---------------- fp16 GEMM (m16n8k16), BK=64, 3-stage cp.async ------------
// mode: 0 = fp32 out, 1 = relu + fp16 out, 2 = fp16 out
template<int BMt, int BNt>
__global__ void __launch_bounds__(256, (BMt==64 ? 4 : 2))
mma_gemm(const __half* __restrict__ A, const __half* __restrict__ W,
         const float* __restrict__ bias, void* __restrict__ Cv,
         int M, int N, int K, int mode)
{
    constexpr int MI   = BMt/32;
    constexpr int NI   = BNt/32;
    constexpr int ACH  = BMt/32;
    constexpr int BCH  = BNt/32;
    constexpr int BCPR = BNt/8;
    constexpr int ASTR = 72;
    constexpr int BSTR = BNt + 8;
    constexpr int A_FL = BMt*ASTR;
    constexpr int B_FL = 64*BSTR;
    constexpr int STG  = A_FL + B_FL;

    extern __shared__ __half smh[];

    int tid  = threadIdx.x;
    int lane = tid & 31;
    int wid  = tid >> 5;
    int bm = blockIdx.y * BMt;
    int bn = blockIdx.x * BNt;
    int wm = (wid >> 2) * (BMt/2);
    int wn = (wid & 3) * (BNt/4);
    int q = lane >> 2;
    int r = lane & 3;

    float acc[MI][NI][4];
    #pragma unroll
    for (int mi = 0; mi < MI; mi++)
        #pragma unroll
        for (int ni = 0; ni < NI; ni++)
            #pragma unroll
            for (int j = 0; j < 4; j++) acc[mi][ni][j] = 0.f;

    int arow[ACH], ac8[ACH]; bool aval[ACH];
    #pragma unroll
    for (int i = 0; i < ACH; i++) {
        int idx = tid + i*256; arow[i] = idx >> 3; ac8[i] = idx & 7;
        aval[i] = (bm + arow[i]) < M;
    }
    int brow[BCH], bc8[BCH];
    #pragma unroll
    for (int i = 0; i < BCH; i++) { int idx = tid + i*256; brow[i] = idx / BCPR; bc8[i] = idx % BCPR; }

    int nkt = K / 64;

    unsigned smem_u32 = (unsigned)__cvta_generic_to_shared(smh);
    unsigned a_lane_off = (unsigned)(((lane & 15) * ASTR + (lane >> 4) * 8) * 2);
    unsigned b_lane_off = (unsigned)(((((lane >> 3) & 1) * 8 + (lane & 7)) * BSTR
                                      + (lane >> 4) * 8) * 2);

    auto load_stage = [&](int slot, int kg) {
        __half* As = smh + slot*STG;
        __half* Bs = As + A_FL;
        #pragma unroll
        for (int i = 0; i < ACH; i++)
            cp_async16(As + arow[i]*ASTR + ac8[i]*8,
                       A + (size_t)(aval[i] ? (bm + arow[i]) : 0) * K + kg + ac8[i]*8, aval[i]);
        #pragma unroll
        for (int i = 0; i < BCH; i++)
            cp_async16(Bs + brow[i]*BSTR + bc8[i]*8,
                       W + (size_t)(kg + brow[i]) * N + bn + bc8[i]*8, true);
    };

    load_stage(0, 0);
    cp_commit();
    if (nkt > 1) load_stage(1, 64);
    cp_commit();

    for (int kt = 0; kt < nkt; kt++) {
        int st = kt % 3;
        if (kt + 2 < nkt) load_stage((kt + 2) % 3, (kt + 2) * 64);
        cp_commit();
        cp_wait<2>();
        __syncthreads();

        unsigned abase = smem_u32 + (unsigned)(st*STG)*2u + (unsigned)(wm*ASTR)*2u + a_lane_off;
        unsigned bbase = smem_u32 + (unsigned)((st*STG + A_FL))*2u + (unsigned)wn*2u + b_lane_off;

        #pragma unroll
        for (int ks = 0; ks < 4; ks++) {
            unsigned af[MI][4], bf[NI][2];
            #pragma unroll
            for (int mi = 0; mi < MI; mi++) {
                LDSM_X4(af[mi][0], af[mi][1], af[mi][2], af[mi][3],
                        abase + (unsigned)((mi*16*ASTR + ks*16)*2));
            }
            #pragma unroll
            for (int nb = 0; nb < NI/2; nb++) {
                LDSM_X4T(bf[2*nb][0], bf[2*nb][1], bf[2*nb+1][0], bf[2*nb+1][1],
                         bbase + (unsigned)((ks*16*BSTR + nb*16)*2));
            }
            #pragma unroll
            for (int mi = 0; mi < MI; mi++)
                #pragma unroll
                for (int ni = 0; ni < NI; ni++)
                    mma_f16(acc[mi][ni], af[mi], bf[ni]);
        }
        __syncthreads();
    }

    #pragma unroll
    for (int mi = 0; mi < MI; mi++) {
        #pragma unroll
        for (int ni = 0; ni < NI; ni++) {
            int row = bm + wm + mi*16 + q;
            int col = bn + wn + ni*8 + r*2;
            float bx = bias[col], by = bias[col+1];
            float v0 = acc[mi][ni][0] + bx;
            float v1 = acc[mi][ni][1] + by;
            float v2 = acc[mi][ni][2] + bx;
            float v3 = acc[mi][ni][3] + by;
            if (mode == 1) {
                v0 = fmaxf(v0, 0.f); v1 = fmaxf(v1, 0.f);
                v2 = fmaxf(v2, 0.f); v3 = fmaxf(v3, 0.f);
            }
            if (mode == 0) {
                float* C = (float*)Cv;
                if (row < M)
                    *(float2*)&C[(size_t)row * N + col] = make_float2(v0, v1);
                if (row + 8 < M)
                    *(float2*)&C[(size_t)(row + 8) * N + col] = make_float2(v2, v3);
            } else {
                __half* Ch = (__half*)Cv;
                if (row < M)
                    *(__half2*)&Ch[(size_t)row * N + col] = __floats2half2_rn(v0, v1);
                if (row + 8 < M)
                    *(__half2*)&Ch[(size_t)(row + 8) * N + col] = __floats2half2_rn(v2, v3);
            }
        }
    }
}

// ---------------- fused GEMM + residual + LayerNorm (N = 256, full row) ----
// y = LN(xres + A@W + bias); writes out (fp32), outh (fp16), qouth = fp16(y+pos)
// Tile 64x256, BK=32, 8 warps (2 row-groups x 4 col-groups), 3-stage cp.async.
#define LN_ASTR 40
#define LN_BSTR 264
#define LN_AFL (64*LN_ASTR)        // 2560 halves
#define LN_BFL (32*LN_BSTR)        // 8448 halves
#define LN_STG (LN_AFL + LN_BFL)   // 11008 halves
#define SMEM_LN (3*LN_STG*2 + 2048)

__global__ void __launch_bounds__(256, 2)
mma_gemm_ln(const __half* __restrict__ A, const __half* __restrict__ W,
            const float* __restrict__ bias, const float* __restrict__ xres,
            const float* __restrict__ g, const float* __restrict__ be,
            float* __restrict__ out, __half* __restrict__ outh,
            const float* __restrict__ pos, __half* __restrict__ qouth,
            int M, int K)
{
    constexpr int N = 256;
    extern __shared__ __half smh[];

    int tid  = threadIdx.x;
    int lane = tid & 31;
    int wid  = tid >> 5;
    int bm = blockIdx.x * 64;
    int wm = (wid >> 2) * 32;
    int wn = (wid & 3) * 64;
    int q = lane >> 2;
    int r = lane & 3;

    float acc[2][8][4];
    #pragma unroll
    for (int mi = 0; mi < 2; mi++)
        #pragma unroll
        for (int ni = 0; ni < 8; ni++)
            #pragma unroll
            for (int j = 0; j < 4; j++) acc[mi][ni][j] = 0.f;

    // A: 64 rows x 32 halves (256 chunks, 1/thread); B: 32 rows x 256 halves (1024 chunks, 4/thread)
    int arow = tid >> 2, ac8 = tid & 3;
    bool aval = (bm + arow) < M;
    int brow[4], bc8[4];
    #pragma unroll
    for (int i = 0; i < 4; i++) { int idx = tid + i*256; brow[i] = idx >> 5; bc8[i] = idx & 31; }

    int nkt = K / 32;

    unsigned smem_u32 = (unsigned)__cvta_generic_to_shared(smh);
    unsigned a_lane_off = (unsigned)(((lane & 15) * LN_ASTR + (lane >> 4) * 8) * 2);
    unsigned b_lane_off = (unsigned)(((((lane >> 3) & 1) * 8 + (lane & 7)) * LN_BSTR
                                      + (lane >> 4) * 8) * 2);

    auto load_stage = [&](int slot, int kg) {
        __half* As = smh + slot*LN_STG;
        __half* Bs = As + LN_AFL;
        cp_async16(As + arow*LN_ASTR + ac8*8,
                   A + (size_t)(aval ? (bm + arow) : 0) * K + kg + ac8*8, aval);
        #pragma unroll
        for (int i = 0; i < 4; i++)
            cp_async16(Bs + brow[i]*LN_BSTR + bc8[i]*8,
                       W + (size_t)(kg + brow[i]) * N + bc8[i]*8, true);
    };

    load_stage(0, 0);
    cp_commit();
    if (nkt > 1) load_stage(1, 32);
    cp_commit();

    for (int kt = 0; kt < nkt; kt++) {
        int st = kt % 3;
        if (kt + 2 < nkt) load_stage((kt + 2) % 3, (kt + 2) * 32);
        cp_commit();
        cp_wait<2>();
        __syncthreads();

        unsigned abase = smem_u32 + (unsigned)(st*LN_STG)*2u + (unsigned)(wm*LN_ASTR)*2u + a_lane_off;
        unsigned bbase = smem_u32 + (unsigned)((st*LN_STG + LN_AFL))*2u + (unsigned)wn*2u + b_lane_off;

        #pragma unroll
        for (int ks = 0; ks < 2; ks++) {
            unsigned af[2][4], bf[8][2];
            #pragma unroll
            for (int mi = 0; mi < 2; mi++) {
                LDSM_X4(af[mi][0], af[mi][1], af[mi][2], af[mi][3],
                        abase + (unsigned)((mi*16*LN_ASTR + ks*16)*2));
            }
            #pragma unroll
            for (int nb = 0; nb < 4; nb++) {
                LDSM_X4T(bf[2*nb][0], bf[2*nb][1], bf[2*nb+1][0], bf[2*nb+1][1],
                         bbase + (unsigned)((ks*16*LN_BSTR + nb*16)*2));
            }
            #pragma unroll
            for (int mi = 0; mi < 2; mi++)
                #pragma unroll
                for (int ni = 0; ni < 8; ni++)
                    mma_f16(acc[mi][ni], af[mi], bf[ni]);
        }
        __syncthreads();
    }

    // ---- fused epilogue: v = xres + acc + bias; LN over full row ----
    float sums[2][2] = {{0.f,0.f},{0.f,0.f}};
    float sqs [2][2] = {{0.f,0.f},{0.f,0.f}};
    #pragma unroll
    for (int mi = 0; mi < 2; mi++) {
        int row0 = bm + wm + mi*16 + q;
        int row1 = row0 + 8;
        #pragma unroll
        for (int ni = 0; ni < 8; ni++) {
            int col = wn + ni*8 + r*2;
            float bx = bias[col], by = bias[col+1];
            float2 x0 = make_float2(0.f, 0.f), x1 = make_float2(0.f, 0.f);
            if (row0 < M) x0 = *(const float2*)&xres[(size_t)row0 * N + col];
            if (row1 < M) x1 = *(const float2*)&xres[(size_t)row1 * N + col];
            float v0 = acc[mi][ni][0] + bx + x0.x;
            float v1 = acc[mi][ni][1] + by + x0.y;
            float v2 = acc[mi][ni][2] + bx + x1.x;
            float v3 = acc[mi][ni][3] + by + x1.y;
            acc[mi][ni][0] = v0; acc[mi][ni][1] = v1;
            acc[mi][ni][2] = v2; acc[mi][ni][3] = v3;
            sums[mi][0] += v0 + v1;      sums[mi][1] += v2 + v3;
            sqs [mi][0] += v0*v0 + v1*v1; sqs[mi][1] += v2*v2 + v3*v3;
        }
    }
    // quad reduce over r (lane bits 0-1)
    #pragma unroll
    for (int o = 1; o <= 2; o <<= 1) {
        #pragma unroll
        for (int mi = 0; mi < 2; mi++)
            #pragma unroll
            for (int h = 0; h < 2; h++) {
                sums[mi][h] += __shfl_xor_sync(0xFFFFFFFFu, sums[mi][h], o);
                sqs [mi][h] += __shfl_xor_sync(0xFFFFFFFFu, sqs [mi][h], o);
            }
    }
    float* redS = (float*)(smh + 3*LN_STG);
    float* redQ = redS + 256;
    __syncthreads();
    if (r == 0) {
        int cw = wid & 3;
        #pragma unroll
        for (int mi = 0; mi < 2; mi++)
            #pragma unroll
            for (int h = 0; h < 2; h++) {
                int lr = wm + mi*16 + q + h*8;
                redS[lr*4 + cw] = sums[mi][h];
                redQ[lr*4 + cw] = sqs[mi][h];
            }
    }
    __syncthreads();

    #pragma unroll
    for (int mi = 0; mi < 2; mi++) {
        int lr0 = wm + mi*16 + q;
        int lr1 = lr0 + 8;
        float s0 = redS[lr0*4] + redS[lr0*4+1] + redS[lr0*4+2] + redS[lr0*4+3];
        float q0 = redQ[lr0*4] + redQ[lr0*4+1] + redQ[lr0*4+2] + redQ[lr0*4+3];
        float s1 = redS[lr1*4] + redS[lr1*4+1] + redS[lr1*4+2] + redS[lr1*4+3];
        float q1 = redQ[lr1*4] + redQ[lr1*4+1] + redQ[lr1*4+2] + redQ[lr1*4+3];
        float mean0 = s0 * (1.f/N);
        float mean1 = s1 * (1.f/N);
        float inv0 = rsqrtf(fmaxf(q0*(1.f/N) - mean0*mean0, 0.f) + 1e-5f);
        float inv1 = rsqrtf(fmaxf(q1*(1.f/N) - mean1*mean1, 0.f) + 1e-5f);
        int row0 = bm + lr0;
        int row1 = bm + lr1;
        #pragma unroll
        for (int ni = 0; ni < 8; ni++) {
            int col = wn + ni*8 + r*2;
            float2 gv = *(const float2*)&g[col];
            float2 bv = *(const float2*)&be[col];
            float y0 = (acc[mi][ni][0] - mean0)*inv0*gv.x + bv.x;
            float y1 = (acc[mi][ni][1] - mean0)*inv0*gv.y + bv.y;
            float y2 = (acc[mi][ni][2] - mean1)*inv1*gv.x + bv.x;
            float y3 = (acc[mi][ni][3] - mean1)*inv1*gv.y + bv.y;
            if (row0 < M) {
                *(float2*)&out[(size_t)row0 * N + col] = make_float2(y0, y1);
                if (outh)
                    *(__half2*)&outh[(size_t)row0 * N + col] = __floats2half2_rn(y0, y1);
                if (qouth) {
                    float2 pv = *(const float2*)&pos[(size_t)row0 * N + col];
                    *(__half2*)&qouth[(size_t)row0 * N + col] = __floats2half2_rn(y0 + pv.x, y1 + pv.y);
                }
            }
            if (row1 < M) {
                *(float2*)&out[(size_t)row1 * N + col] = make_float2(y2, y3);
                if (outh)
                    *(__half2*)&outh[(size_t)row1 * N + col] = __floats2half2_rn(y2, y3);
                if (qouth) {
                    float2 pv = *(const float2*)&pos[(size_t)row1 * N + col];
                    *(__half2*)&qouth[(size_t)row1 * N + col] = __floats2half2_rn(y2 + pv.x, y3 + pv.y);
                }
            }
        }
    }
}

// ---------------- deformable sampling, fp16 value, half4 loads ----------------
__global__ void sample_kernel()
{
    int warpIdx = (blockIdx.x * blockDim.x + threadIdx.x) >> 5;
    int lane  = threadIdx.x & 31;
    if (warpIdx >= M_ * NH_) return;
    int h  = warpIdx / M_;
    int bs = warpIdx - h * M_;
    int b  = bs / S_;
    int s  = bs % S_;
    int eg = lane & 7;
    int pg = lane >> 3;

    int lvl_q, iq;
    if (s < 9216)       { lvl_q = 0; iq = s;         }
    else if (s < 10368) { lvl_q = 1; iq = s - 9216;  }
    else if (s < 10512) { lvl_q = 2; iq = s - 10368; }
    else                { lvl_q = 3; iq = s - 10512; }
    int Wq = c_LW[lvl_q], Hq = c_LH[lvl_q], Dq = c_LD[lvl_q];
    int xq = iq % Wq;
    int t  = iq / Wq;
    int yq = t % Hq;
    int zq = t / Hq;
    float rx = (xq + 0.5f) / (float)Wq;
    float ry = (yq + 0.5f) / (float)Hq;
    float rz = (zq + 0.5f) / (float)Dq;

    const float4* lg4 = (const float4*)(g_oa + (size_t)bs * 512 + 384 + h * 16);
    float lv[16];
    {
        float4 v0 = lg4[0], v1 = lg4[1], v2 = lg4[2], v3 = lg4[3];
        lv[0]=v0.x; lv[1]=v0.y; lv[2]=v0.z; lv[3]=v0.w;
        lv[4]=v1.x; lv[5]=v1.y; lv[6]=v1.z; lv[7]=v1.w;
        lv[8]=v2.x; lv[9]=v2.y; lv[10]=v2.z; lv[11]=v2.w;
        lv[12]=v3.x; lv[13]=v3.y; lv[14]=v3.z; lv[15]=v3.w;
    }
    float mx = -1e30f;
    #pragma unroll
    for (int j = 0; j < 16; j++) mx = fmaxf(mx, lv[j]);
    float ssum = 0.f;
    #pragma unroll
    for (int j = 0; j < 16; j++) { lv[j] = __expf(lv[j] - mx); ssum += lv[j]; }
    float inv = 1.f / ssum;

    const float* offp = g_oa + (size_t)bs * 512 + h * (NL_*NP_*3);

    const int LDc[4]  = {4, 2, 1, 1};
    const int LHc[4]  = {48, 24, 12, 6};
    const int LWc[4]  = {48, 24, 12, 6};
    const int LS0c[4] = {0, 9216, 10368, 10512};

    float4 acc = make_float4(0.f, 0.f, 0.f, 0.f);

    #pragma unroll
    for (int lvl = 0; lvl < 4; lvl++) {
        const int Dl = LDc[lvl], Hl = LHc[lvl], Wl = LWc[lvl];
        const __half* vb = g_valh + ((size_t)b * S_ + LS0c[lvl]) * E_ + h * HD_ + eg * 4;

        float aw = lv[lvl*4 + pg] * inv;
        float ox = offp[lvl*12 + pg*3 + 0];
        float oy = offp[lvl*12 + pg*3 + 1];
        float oz = offp[lvl*12 + pg*3 + 2];
        float cx = rx * (float)Wl + ox - 0.5f;
        float cy = ry * (float)Hl + oy - 0.5f;
        float cz = rz * (float)Dl + oz - 0.5f;
        float xf = floorf(cx), yf = floorf(cy), zf = floorf(cz);
        float fx = cx - xf, fy = cy - yf, fz = cz - zf;
        int x0 = (int)xf, y0 = (int)yf, z0 = (int)zf;

        #pragma unroll
        for (int dz = 0; dz < 2; dz++) {
            int iz = z0 + dz;
            float wz = dz ? fz : 1.f - fz;
            bool vz = (iz >= 0) & (iz < Dl);
            int cz_i = min(max(iz, 0), Dl - 1);
            #pragma unroll
            for (int dy = 0; dy < 2; dy++) {
                int iy = y0 + dy;
                float wy = dy ? fy : 1.f - fy;
                bool vy = (iy >= 0) & (iy < Hl);
                int cy_i = min(max(iy, 0), Hl - 1);
                #pragma unroll
                for (int dx = 0; dx < 2; dx++) {
                    int ix = x0 + dx;
                    float wx = dx ? fx : 1.f - fx;
                    bool vx = (ix >= 0) & (ix < Wl);
                    int cx_i = min(max(ix, 0), Wl - 1);
                    float wgt = (vz & vy & vx) ? (aw * wx * wy * wz) : 0.f;
                    int idx = (cz_i*Hl + cy_i)*Wl + cx_i;
                    uint2 raw = *(const uint2*)(vb + (size_t)idx * E_);
                    __half2 h0 = *reinterpret_cast<const __half2*>(&raw.x);
                    __half2 h1 = *reinterpret_cast<const __half2*>(&raw.y);
                    float2 f0 = __half22float2(h0);
                    float2 f1 = __half22float2(h1);
                    acc.x += wgt * f0.x;
                    acc.y += wgt * f0.y;
                    acc.z += wgt * f1.x;
                    acc.w += wgt * f1.y;
                }
            }
        }
    }

    #pragma unroll
    for (int o = 8; o <= 16; o <<= 1) {
        acc.x += __shfl_xor_sync(0xFFFFFFFFu, acc.x, o);
        acc.y += __shfl_xor_sync(0xFFFFFFFFu, acc.y, o);
        acc.z += __shfl_xor_sync(0xFFFFFFFFu, acc.z, o);
        acc.w += __shfl_xor_sync(0xFFFFFFFFu, acc.w, o);
    }

    if (lane < 8) {
        store_half4(g_samh + (size_t)bs * E_ + h * HD_ + lane * 4,
                    acc.x, acc.y, acc.z, acc.w);
    }
}

// ---------------- host launcher ----------------
#define SMEM128 (3*(128*72 + 64*136)*2)   // 107520
#define SMEM64  (3*(64*72 + 64*72)*2)     // 55296

extern "C" void kernel_launch(void* const* d_in, const int* in_sizes, int n_in,
                              void* d_out, int out_size)
{
    (void)in_sizes; (void)n_in; (void)out_size;
    const float* f0 = (const float*)d_in[0];
    const float* p0 = (const float*)d_in[1];
    const float* f1 = (const float*)d_in[2];
    const float* p1 = (const float*)d_in[3];
    const float* f2 = (const float*)d_in[4];
    const float* p2 = (const float*)d_in[5];
    const float* f3 = (const float*)d_in[6];
    const float* p3 = (const float*)d_in[7];
    const float* le = (const float*)d_in[8];
    const float* W_off  = (const float*)d_in[9];
    const float* b_off  = (const float*)d_in[10];
    const float* W_attn = (const float*)d_in[11];
    const float* b_attn = (const float*)d_in[12];
    const float* W_val  = (const float*)d_in[13];
    const float* b_val  = (const float*)d_in[14];
    const float* W_out  = (const float*)d_in[15];
    const float* b_out  = (const float*)d_in[16];
    const float* ln1_g  = (const float*)d_in[17];
    const float* ln1_b  = (const float*)d_in[18];
    const float* W_ff1  = (const float*)d_in[19];
    const float* b_ff1  = (const float*)d_in[20];
    const float* W_ff2  = (const float*)d_in[21];
    const float* b_ff2  = (const float*)d_in[22];
    const float* ln2_g  = (const float*)d_in[23];
    const float* ln2_b  = (const float*)d_in[24];

    float  *px, *ppos, *poa, *pbqa;
    __half *pxh, *pqh, *pvalh, *psamh, *phidh;
    __half *pWval, *pWqa, *pWout, *pWff1, *pWff2;
    cudaGetSymbolAddress((void**)&px,    g_x);
    cudaGetSymbolAddress((void**)&pxh,   g_xh);
    cudaGetSymbolAddress((void**)&ppos,  g_pos);
    cudaGetSymbolAddress((void**)&pqh,   g_qh);
    cudaGetSymbolAddress((void**)&pvalh, g_valh);
    cudaGetSymbolAddress((void**)&psamh, g_samh);
    cudaGetSymbolAddress((void**)&phidh, g_hidh);
    cudaGetSymbolAddress((void**)&poa,   g_oa);
    cudaGetSymbolAddress((void**)&pWval, g_Wval);
    cudaGetSymbolAddress((void**)&pWqa,  g_Wqa);
    cudaGetSymbolAddress((void**)&pWout, g_Wout);
    cudaGetSymbolAddress((void**)&pWff1, g_Wff1);
    cudaGetSymbolAddress((void**)&pWff2, g_Wff2);
    cudaGetSymbolAddress((void**)&pbqa,  g_bqa);

    cudaFuncSetAttribute(mma_gemm<128,128>, cudaFuncAttributeMaxDynamicSharedMemorySize, SMEM128);
    cudaFuncSetAttribute(mma_gemm<64,64>,   cudaFuncAttributeMaxDynamicSharedMemorySize, SMEM64);
    cudaFuncSetAttribute(mma_gemm_ln,       cudaFuncAttributeMaxDynamicSharedMemorySize, SMEM_LN);

    // launch 1: merged weight prep
    prep_weights<<<(PREP_TOT + 255)/256, 256>>>(W_val, W_out, W_ff1, W_ff2,
                                                W_off, W_attn, b_off, b_attn);

    // launches 2-5: transposing init, one per level
    {
        dim3 blk(32, 32);
        init_t_kernel<<<dim3(288, 8, B_), blk>>>(f0, p0, le + 0*E_, 9216, 0);
        init_t_kernel<<<dim3( 36, 8, B_), blk>>>(f1, p1, le + 1*E_, 1152, 9216);
        init_t_kernel<<<dim3(  5, 8, B_), blk>>>(f2, p2, le + 2*E_,  144, 10368);
        init_t_kernel<<<dim3(  2, 8, B_), blk>>>(f3, p3, le + 3*E_,   36, 10512);
    }

    const int GM64  = (M_ + 63) / 64;    // 330
    const int GM128 = (M_ + 127) / 128;  // 165

    for (int l = 0; l < NLAYERS_; l++) {
        // value proj -> fp16 out
        mma_gemm<64,64><<<dim3(E_/64, GM64), 256, SMEM64>>>(pxh, pWval + (size_t)l*E_*E_,
                                           b_val + l*E_, pvalh, M_, E_, E_, 2);
        // offsets + attn logits -> fp32 out
        mma_gemm<128,128><<<dim3(512/128, GM128), 256, SMEM128>>>(pqh, pWqa + (size_t)l*E_*512,
                                            pbqa + l*512, poa, M_, 512, E_, 0);

        sample_kernel<<<(M_ * NH_ * 32) / 256, 256>>>();

        // fused out-proj + residual + LN1 -> px (fp32) + pxh (fp16)
        mma_gemm_ln<<<GM64, 256, SMEM_LN>>>(psamh, pWout + (size_t)l*E_*E_,
                                            b_out + l*E_, px,
                                            ln1_g + l*E_, ln1_b + l*E_,
                                            px, pxh, (const float*)0, (__half*)0,
                                            M_, E_);

        // ff1: relu + fp16 out
        mma_gemm<128,128><<<dim3(DF_/128, GM128), 256, SMEM128>>>(pxh, pWff1 + (size_t)l*E_*DF_,
                                            b_ff1 + l*DF_, phidh, M_, DF_, E_, 1);

        // fused ff2 + residual + LN2
        if (l == NLAYERS_ - 1) {
            mma_gemm_ln<<<GM64, 256, SMEM_LN>>>(phidh, pWff2 + (size_t)l*DF_*E_,
                                                b_ff2 + l*E_, px,
                                                ln2_g + l*E_, ln2_b + l*E_,
                                                (float*)d_out, (__half*)0,
                                                (const float*)0, (__half*)0,
                                                M_, DF_);
        } else {
            mma_gemm_ln<<<GM64, 256, SMEM_LN>>>(phidh, pWff2 + (size_t)l*DF_*E_,
                                                b_ff2 + l*E_, px,
                                                ln2_g + l*E_, ln2_b + l*E_,
                                                px, pxh, ppos, pqh,
                                                M_, DF_);
        }
    }
}

// round 16
// speedup vs baseline: 1.0375x; 1.0375x over previous
#include <cuda_runtime.h>
#include <cuda_fp16.h>
#include <math.h>
#include <stdint.h>

// ---------------- problem constants ----------------
#define B_ 2
#define E_ 256
#define NH_ 8
#define NL_ 4
#define NP_ 4
#define DF_ 1024
#define NLAYERS_ 6
#define HD_ 32
#define S_ 10548
#define M_ (B_*S_)          // 21096 query rows

__device__ __constant__ int c_LD[4] = {4, 2, 1, 1};
__device__ __constant__ int c_LH[4] = {48, 24, 12, 6};
__device__ __constant__ int c_LW[4] = {48, 24, 12, 6};

// ---------------- scratch (allocation-free) ----------------
__device__ float  g_x   [M_*E_];    // fp32 residual stream
__device__ __half g_xh  [M_*E_];    // fp16 copy of x (GEMM A)
__device__ float  g_pos [M_*E_];
__device__ __half g_qh  [M_*E_];    // fp16 q = x + pos (GEMM A)
__device__ __half g_valh[M_*E_];    // fp16 value tensor
__device__ __half g_samh[M_*E_];    // fp16 sampler output (GEMM A)
__device__ float  g_tmp [M_*E_];
__device__ float  g_oa  [M_*512];   // packed: [0,384) offsets, [384,512) attn logits
__device__ __half g_hidh[M_*DF_];   // fp16 hidden (GEMM A)

// fp16 weights [K,N] row-major
__device__ __half g_Wval[NLAYERS_*E_*E_];
__device__ __half g_Wqa [NLAYERS_*E_*512];
__device__ __half g_Wout[NLAYERS_*E_*E_];
__device__ __half g_Wff1[NLAYERS_*E_*DF_];
__device__ __half g_Wff2[NLAYERS_*DF_*E_];
__device__ float  g_bqa [NLAYERS_*512];

// ---------------- helpers ----------------
__device__ __forceinline__ void mma_f16(float c[4], const unsigned a[4], const unsigned b[2])
{
    asm volatile("mma.sync.aligned.m16n8k16.row.col.f32.f16.f16.f32 "
        "{%0,%1,%2,%3}, {%4,%5,%6,%7}, {%8,%9}, {%0,%1,%2,%3};\n"
        : "+f"(c[0]), "+f"(c[1]), "+f"(c[2]), "+f"(c[3])
        : "r"(a[0]), "r"(a[1]), "r"(a[2]), "r"(a[3]), "r"(b[0]), "r"(b[1]));
}

__device__ __forceinline__ void cp_async16(void* smem, const void* gmem, bool valid)
{
    unsigned saddr = (unsigned)__cvta_generic_to_shared(smem);
    int sz = valid ? 16 : 0;
    asm volatile("cp.async.cg.shared.global [%0], [%1], 16, %2;\n"
                 :: "r"(saddr), "l"(gmem), "r"(sz));
}
__device__ __forceinline__ void cp_commit() { asm volatile("cp.async.commit_group;\n"); }
template<int N> __device__ __forceinline__ void cp_wait() { asm volatile("cp.async.wait_group %0;\n" :: "n"(N)); }

#define LDSM_X4(r0,r1,r2,r3,addr) \
    asm volatile("ldmatrix.sync.aligned.m8n8.x4.shared.b16 {%0,%1,%2,%3}, [%4];\n" \
        : "=r"(r0), "=r"(r1), "=r"(r2), "=r"(r3) : "r"(addr))

#define LDSM_X4T(r0,r1,r2,r3,addr) \
    asm volatile("ldmatrix.sync.aligned.m8n8.x4.trans.shared.b16 {%0,%1,%2,%3}, [%4];\n" \
        : "=r"(r0), "=r"(r1), "=r"(r2), "=r"(r3) : "r"(addr))

__device__ __forceinline__ void store_half4(__half* p, float a, float b, float c, float d)
{
    __half2 h01 = __floats2half2_rn(a, b);
    __half2 h23 = __floats2half2_rn(c, d);
    uint2 u;
    u.x = *reinterpret_cast<unsigned*>(&h01);
    u.y = *reinterpret_cast<unsigned*>(&h23);
    *reinterpret_cast<uint2*>(p) = u;
}

// ---------------- merged weight prep (single launch) ----------------
__global__ void prep_weights(const float* __restrict__ W_val, const float* __restrict__ W_out,
                             const float* __restrict__ W_ff1, const float* __restrict__ W_ff2,
                             const float* __restrict__ W_off, const float* __restrict__ W_attn,
                             const float* __restrict__ b_off, const float* __restrict__ b_attn)
{
    const int nVal = NLAYERS_*E_*E_;
    const int nFf  = NLAYERS_*E_*DF_;
    const int nQa  = NLAYERS_*E_*512;
    int i = blockIdx.x * blockDim.x + threadIdx.x;
    if (i < nVal) { g_Wval[i] = __float2half_rn(W_val[i]); return; }
    i -= nVal;
    if (i < nVal) { g_Wout[i] = __float2half_rn(W_out[i]); return; }
    i -= nVal;
    if (i < nFf)  { g_Wff1[i] = __float2half_rn(W_ff1[i]); return; }
    i -= nFf;
    if (i < nFf)  { g_Wff2[i] = __float2half_rn(W_ff2[i]); return; }
    i -= nFf;
    if (i < nQa) {
        int l = i / (E_ * 512);
        int rem = i - l * E_ * 512;
        int k = rem >> 9;
        int c = rem & 511;
        float v = (c < 384) ? W_off[(size_t)l*E_*384 + k*384 + c]
                            : W_attn[(size_t)l*E_*128 + k*128 + (c - 384)];
        g_Wqa[i] = __float2half_rn(v);
        return;
    }
    i -= nQa;
    if (i < NLAYERS_ * 512) {
        int l = i >> 9;
        int c = i & 511;
        g_bqa[i] = (c < 384) ? b_off[l*384 + c] : b_attn[l*128 + (c - 384)];
    }
}
#define PREP_TOT (2*NLAYERS_*E_*E_ + 2*NLAYERS_*E_*DF_ + NLAYERS_*E_*512 + NLAYERS_*512)

// ---------------- merged coalesced transposing init (one launch) ----------
// blockIdx.x ranges: [0,288) lvl0, [288,324) lvl1, [324,329) lvl2, [329,331) lvl3
__global__ void init_all_kernel(const float* __restrict__ f0, const float* __restrict__ p0,
                                const float* __restrict__ f1, const float* __restrict__ p1,
                                const float* __restrict__ f2, const float* __restrict__ p2,
                                const float* __restrict__ f3, const float* __restrict__ p3,
                                const float* __restrict__ le)
{
    __shared__ float tf[32][33];
    __shared__ float tp[32][33];
    int bx = blockIdx.x;
    const float *f, *p, *le_row;
    int n, s0, xb;
    if (bx < 288)      { f = f0; p = p0; n = 9216; s0 = 0;     xb = bx;       le_row = le; }
    else if (bx < 324) { f = f1; p = p1; n = 1152; s0 = 9216;  xb = bx - 288; le_row = le + E_; }
    else if (bx < 329) { f = f2; p = p2; n = 144;  s0 = 10368; xb = bx - 324; le_row = le + 2*E_; }
    else               { f = f3; p = p3; n = 36;   s0 = 10512; xb = bx - 329; le_row = le + 3*E_; }

    int i0 = xb * 32;
    int e0 = blockIdx.y * 32;
    int b  = blockIdx.z;
    int tx = threadIdx.x, ty = threadIdx.y;

    int ig = i0 + tx;
    int eg = e0 + ty;
    if (ig < n) {
        size_t src = (size_t)(b*E_ + eg) * n + ig;
        tf[ty][tx] = f[src];
        tp[ty][tx] = p[src];
    }
    __syncthreads();

    int iw = i0 + ty;
    int ew = e0 + tx;
    if (iw < n) {
        size_t dst = (size_t)(b*S_ + s0 + iw) * E_ + ew;
        float xv = tf[tx][ty];
        float pv = tp[tx][ty] + le_row[ew];
        g_x[dst]   = xv;
        g_xh[dst]  = __float2half_rn(xv);
        g_pos[dst] = pv;
        g_qh[dst]  = __float2half_rn(xv + pv);
    }
}

// ---------------- fp16 tensor-core GEMM (m16n8k16), BK=64, 3-stage cp.async --
// mode: 0 = fp32 out, 1 = relu + fp16 out, 2 = fp16 out
template<int BMt, int BNt>
__global__ void __launch_bounds__(256, (BMt==64 ? 4 : 2))
mma_gemm(const __half* __restrict__ A, const __half* __restrict__ W,
         const float* __restrict__ bias, void* __restrict__ Cv,
         int M, int N, int K, int mode)
{
    constexpr int MI   = BMt/32;
    constexpr int NI   = BNt/32;
    constexpr int ACH  = BMt/32;
    constexpr int BCH  = BNt/32;
    constexpr int BCPR = BNt/8;
    constexpr int ASTR = 72;
    constexpr int BSTR = BNt + 8;
    constexpr int A_FL = BMt*ASTR;
    constexpr int B_FL = 64*BSTR;
    constexpr int STG  = A_FL + B_FL;

    extern __shared__ __half smh[];

    int tid  = threadIdx.x;
    int lane = tid & 31;
    int wid  = tid >> 5;
    int bm = blockIdx.y * BMt;
    int bn = blockIdx.x * BNt;
    int wm = (wid >> 2) * (BMt/2);
    int wn = (wid & 3) * (BNt/4);
    int q = lane >> 2;
    int r = lane & 3;

    float acc[MI][NI][4];
    #pragma unroll
    for (int mi = 0; mi < MI; mi++)
        #pragma unroll
        for (int ni = 0; ni < NI; ni++)
            #pragma unroll
            for (int j = 0; j < 4; j++) acc[mi][ni][j] = 0.f;

    int arow[ACH], ac8[ACH]; bool aval[ACH];
    #pragma unroll
    for (int i = 0; i < ACH; i++) {
        int idx = tid + i*256; arow[i] = idx >> 3; ac8[i] = idx & 7;
        aval[i] = (bm + arow[i]) < M;
    }
    int brow[BCH], bc8[BCH];
    #pragma unroll
    for (int i = 0; i < BCH; i++) { int idx = tid + i*256; brow[i] = idx / BCPR; bc8[i] = idx % BCPR; }

    int nkt = K / 64;

    unsigned smem_u32 = (unsigned)__cvta_generic_to_shared(smh);
    unsigned a_lane_off = (unsigned)(((lane & 15) * ASTR + (lane >> 4) * 8) * 2);
    unsigned b_lane_off = (unsigned)(((((lane >> 3) & 1) * 8 + (lane & 7)) * BSTR
                                      + (lane >> 4) * 8) * 2);

    auto load_stage = [&](int slot, int kg) {
        __half* As = smh + slot*STG;
        __half* Bs = As + A_FL;
        #pragma unroll
        for (int i = 0; i < ACH; i++)
            cp_async16(As + arow[i]*ASTR + ac8[i]*8,
                       A + (size_t)(aval[i] ? (bm + arow[i]) : 0) * K + kg + ac8[i]*8, aval[i]);
        #pragma unroll
        for (int i = 0; i < BCH; i++)
            cp_async16(Bs + brow[i]*BSTR + bc8[i]*8,
                       W + (size_t)(kg + brow[i]) * N + bn + bc8[i]*8, true);
    };

    load_stage(0, 0);
    cp_commit();
    if (nkt > 1) load_stage(1, 64);
    cp_commit();

    for (int kt = 0; kt < nkt; kt++) {
        int st = kt % 3;
        if (kt + 2 < nkt) load_stage((kt + 2) % 3, (kt + 2) * 64);
        cp_commit();
        cp_wait<2>();
        __syncthreads();

        unsigned abase = smem_u32 + (unsigned)(st*STG)*2u + (unsigned)(wm*ASTR)*2u + a_lane_off;
        unsigned bbase = smem_u32 + (unsigned)((st*STG + A_FL))*2u + (unsigned)wn*2u + b_lane_off;

        #pragma unroll
        for (int ks = 0; ks < 4; ks++) {
            unsigned af[MI][4], bf[NI][2];
            #pragma unroll
            for (int mi = 0; mi < MI; mi++) {
                LDSM_X4(af[mi][0], af[mi][1], af[mi][2], af[mi][3],
                        abase + (unsigned)((mi*16*ASTR + ks*16)*2));
            }
            #pragma unroll
            for (int nb = 0; nb < NI/2; nb++) {
                LDSM_X4T(bf[2*nb][0], bf[2*nb][1], bf[2*nb+1][0], bf[2*nb+1][1],
                         bbase + (unsigned)((ks*16*BSTR + nb*16)*2));
            }
            #pragma unroll
            for (int mi = 0; mi < MI; mi++)
                #pragma unroll
                for (int ni = 0; ni < NI; ni++)
                    mma_f16(acc[mi][ni], af[mi], bf[ni]);
        }
        __syncthreads();
    }

    #pragma unroll
    for (int mi = 0; mi < MI; mi++) {
        #pragma unroll
        for (int ni = 0; ni < NI; ni++) {
            int row = bm + wm + mi*16 + q;
            int col = bn + wn + ni*8 + r*2;
            float bx = bias[col], by = bias[col+1];
            float v0 = acc[mi][ni][0] + bx;
            float v1 = acc[mi][ni][1] + by;
            float v2 = acc[mi][ni][2] + bx;
            float v3 = acc[mi][ni][3] + by;
            if (mode == 1) {
                v0 = fmaxf(v0, 0.f); v1 = fmaxf(v1, 0.f);
                v2 = fmaxf(v2, 0.f); v3 = fmaxf(v3, 0.f);
            }
            if (mode == 0) {
                float* C = (float*)Cv;
                if (row < M)
                    *(float2*)&C[(size_t)row * N + col] = make_float2(v0, v1);
                if (row + 8 < M)
                    *(float2*)&C[(size_t)(row + 8) * N + col] = make_float2(v2, v3);
            } else {
                __half* Ch = (__half*)Cv;
                if (row < M)
                    *(__half2*)&Ch[(size_t)row * N + col] = __floats2half2_rn(v0, v1);
                if (row + 8 < M)
                    *(__half2*)&Ch[(size_t)(row + 8) * N + col] = __floats2half2_rn(v2, v3);
            }
        }
    }
}

// ---------------- deformable sampling, fp16 value, half4 loads ----------------
__global__ void sample_kernel()
{
    int warpIdx = (blockIdx.x * blockDim.x + threadIdx.x) >> 5;
    int lane  = threadIdx.x & 31;
    if (warpIdx >= M_ * NH_) return;
    int h  = warpIdx / M_;
    int bs = warpIdx - h * M_;
    int b  = bs / S_;
    int s  = bs % S_;
    int eg = lane & 7;
    int pg = lane >> 3;

    int lvl_q, iq;
    if (s < 9216)       { lvl_q = 0; iq = s;         }
    else if (s < 10368) { lvl_q = 1; iq = s - 9216;  }
    else if (s < 10512) { lvl_q = 2; iq = s - 10368; }
    else                { lvl_q = 3; iq = s - 10512; }
    int Wq = c_LW[lvl_q], Hq = c_LH[lvl_q], Dq = c_LD[lvl_q];
    int xq = iq % Wq;
    int t  = iq / Wq;
    int yq = t % Hq;
    int zq = t / Hq;
    float rx = (xq + 0.5f) / (float)Wq;
    float ry = (yq + 0.5f) / (float)Hq;
    float rz = (zq + 0.5f) / (float)Dq;

    const float4* lg4 = (const float4*)(g_oa + (size_t)bs * 512 + 384 + h * 16);
    float lv[16];
    {
        float4 v0 = lg4[0], v1 = lg4[1], v2 = lg4[2], v3 = lg4[3];
        lv[0]=v0.x; lv[1]=v0.y; lv[2]=v0.z; lv[3]=v0.w;
        lv[4]=v1.x; lv[5]=v1.y; lv[6]=v1.z; lv[7]=v1.w;
        lv[8]=v2.x; lv[9]=v2.y; lv[10]=v2.z; lv[11]=v2.w;
        lv[12]=v3.x; lv[13]=v3.y; lv[14]=v3.z; lv[15]=v3.w;
    }
    float mx = -1e30f;
    #pragma unroll
    for (int j = 0; j < 16; j++) mx = fmaxf(mx, lv[j]);
    float ssum = 0.f;
    #pragma unroll
    for (int j = 0; j < 16; j++) { lv[j] = __expf(lv[j] - mx); ssum += lv[j]; }
    float inv = 1.f / ssum;

    const float* offp = g_oa + (size_t)bs * 512 + h * (NL_*NP_*3);

    const int LDc[4]  = {4, 2, 1, 1};
    const int LHc[4]  = {48, 24, 12, 6};
    const int LWc[4]  = {48, 24, 12, 6};
    const int LS0c[4] = {0, 9216, 10368, 10512};

    float4 acc = make_float4(0.f, 0.f, 0.f, 0.f);

    #pragma unroll
    for (int lvl = 0; lvl < 4; lvl++) {
        const int Dl = LDc[lvl], Hl = LHc[lvl], Wl = LWc[lvl];
        const __half* vb = g_valh + ((size_t)b * S_ + LS0c[lvl]) * E_ + h * HD_ + eg * 4;

        float aw = lv[lvl*4 + pg] * inv;
        float ox = offp[lvl*12 + pg*3 + 0];
        float oy = offp[lvl*12 + pg*3 + 1];
        float oz = offp[lvl*12 + pg*3 + 2];
        float cx = rx * (float)Wl + ox - 0.5f;
        float cy = ry * (float)Hl + oy - 0.5f;
        float cz = rz * (float)Dl + oz - 0.5f;
        float xf = floorf(cx), yf = floorf(cy), zf = floorf(cz);
        float fx = cx - xf, fy = cy - yf, fz = cz - zf;
        int x0 = (int)xf, y0 = (int)yf, z0 = (int)zf;

        #pragma unroll
        for (int dz = 0; dz < 2; dz++) {
            int iz = z0 + dz;
            float wz = dz ? fz : 1.f - fz;
            bool vz = (iz >= 0) & (iz < Dl);
            int cz_i = min(max(iz, 0), Dl - 1);
            #pragma unroll
            for (int dy = 0; dy < 2; dy++) {
                int iy = y0 + dy;
                float wy = dy ? fy : 1.f - fy;
                bool vy = (iy >= 0) & (iy < Hl);
                int cy_i = min(max(iy, 0), Hl - 1);
                #pragma unroll
                for (int dx = 0; dx < 2; dx++) {
                    int ix = x0 + dx;
                    float wx = dx ? fx : 1.f - fx;
                    bool vx = (ix >= 0) & (ix < Wl);
                    int cx_i = min(max(ix, 0), Wl - 1);
                    float wgt = (vz & vy & vx) ? (aw * wx * wy * wz) : 0.f;
                    int idx = (cz_i*Hl + cy_i)*Wl + cx_i;
                    uint2 raw = *(const uint2*)(vb + (size_t)idx * E_);
                    __half2 h0 = *reinterpret_cast<const __half2*>(&raw.x);
                    __half2 h1 = *reinterpret_cast<const __half2*>(&raw.y);
                    float2 f0 = __half22float2(h0);
                    float2 f1 = __half22float2(h1);
                    acc.x += wgt * f0.x;
                    acc.y += wgt * f0.y;
                    acc.z += wgt * f1.x;
                    acc.w += wgt * f1.y;
                }
            }
        }
    }

    #pragma unroll
    for (int o = 8; o <= 16; o <<= 1) {
        acc.x += __shfl_xor_sync(0xFFFFFFFFu, acc.x, o);
        acc.y += __shfl_xor_sync(0xFFFFFFFFu, acc.y, o);
        acc.z += __shfl_xor_sync(0xFFFFFFFFu, acc.z, o);
        acc.w += __shfl_xor_sync(0xFFFFFFFFu, acc.w, o);
    }

    if (lane < 8) {
        store_half4(g_samh + (size_t)bs * E_ + h * HD_ + lane * 4,
                    acc.x, acc.y, acc.z, acc.w);
    }
}

// ---------------- fused residual + LayerNorm: warp-per-row, 8 rows/block ----
__global__ void __launch_bounds__(256)
ln8_kernel(const float* __restrict__ x, const float* __restrict__ r,
           const float* __restrict__ g, const float* __restrict__ be,
           float* __restrict__ out, __half* __restrict__ outh,
           const float* __restrict__ pos, __half* __restrict__ qouth)
{
    int wid  = threadIdx.x >> 5;
    int lane = threadIdx.x & 31;
    int row  = blockIdx.x * 8 + wid;   // M_ = 21096 = 2637 * 8
    size_t base = (size_t)row * E_;
    int c0 = lane * 4;
    int c1 = 128 + lane * 4;

    float4 xa = *(const float4*)(x + base + c0);
    float4 xb = *(const float4*)(x + base + c1);
    float4 ra = *(const float4*)(r + base + c0);
    float4 rb = *(const float4*)(r + base + c1);
    float4 va = make_float4(xa.x+ra.x, xa.y+ra.y, xa.z+ra.z, xa.w+ra.w);
    float4 vb = make_float4(xb.x+rb.x, xb.y+rb.y, xb.z+rb.z, xb.w+rb.w);

    float ssum = va.x+va.y+va.z+va.w + vb.x+vb.y+vb.z+vb.w;
    #pragma unroll
    for (int o = 16; o > 0; o >>= 1) ssum += __shfl_xor_sync(0xFFFFFFFFu, ssum, o);
    float mean = ssum * (1.f / E_);

    float4 da = make_float4(va.x-mean, va.y-mean, va.z-mean, va.w-mean);
    float4 db = make_float4(vb.x-mean, vb.y-mean, vb.z-mean, vb.w-mean);
    float vsum = da.x*da.x+da.y*da.y+da.z*da.z+da.w*da.w
               + db.x*db.x+db.y*db.y+db.z*db.z+db.w*db.w;
    #pragma unroll
    for (int o = 16; o > 0; o >>= 1) vsum += __shfl_xor_sync(0xFFFFFFFFu, vsum, o);
    float inv = rsqrtf(vsum * (1.f / E_) + 1e-5f);

    float4 ga = *(const float4*)(g + c0);
    float4 gb = *(const float4*)(g + c1);
    float4 ba = *(const float4*)(be + c0);
    float4 bb = *(const float4*)(be + c1);

    float4 ya = make_float4(da.x*inv*ga.x + ba.x, da.y*inv*ga.y + ba.y,
                            da.z*inv*ga.z + ba.z, da.w*inv*ga.w + ba.w);
    float4 yb = make_float4(db.x*inv*gb.x + bb.x, db.y*inv*gb.y + bb.y,
                            db.z*inv*gb.z + bb.z, db.w*inv*gb.w + bb.w);

    *(float4*)(out + base + c0) = ya;
    *(float4*)(out + base + c1) = yb;

    if (outh) {
        store_half4(outh + base + c0, ya.x, ya.y, ya.z, ya.w);
        store_half4(outh + base + c1, yb.x, yb.y, yb.z, yb.w);
    }
    if (qouth) {
        float4 pa = *(const float4*)(pos + base + c0);
        float4 pb = *(const float4*)(pos + base + c1);
        store_half4(qouth + base + c0, ya.x + pa.x, ya.y + pa.y, ya.z + pa.z, ya.w + pa.w);
        store_half4(qouth + base + c1, yb.x + pb.x, yb.y + pb.y, yb.z + pb.z, yb.w + pb.w);
    }
}

// ---------------- host launcher ----------------
// smem bytes = 3 * (BM*72 + 64*(BN+8)) * 2
#define SMEM128 (3*(128*72 + 64*136)*2)   // 107520
#define SMEM64  (3*(64*72 + 64*72)*2)     // 55296

extern "C" void kernel_launch(void* const* d_in, const int* in_sizes, int n_in,
                              void* d_out, int out_size)
{
    (void)in_sizes; (void)n_in; (void)out_size;
    const float* f0 = (const float*)d_in[0];
    const float* p0 = (const float*)d_in[1];
    const float* f1 = (const float*)d_in[2];
    const float* p1 = (const float*)d_in[3];
    const float* f2 = (const float*)d_in[4];
    const float* p2 = (const float*)d_in[5];
    const float* f3 = (const float*)d_in[6];
    const float* p3 = (const float*)d_in[7];
    const float* le = (const float*)d_in[8];
    const float* W_off  = (const float*)d_in[9];
    const float* b_off  = (const float*)d_in[10];
    const float* W_attn = (const float*)d_in[11];
    const float* b_attn = (const float*)d_in[12];
    const float* W_val  = (const float*)d_in[13];
    const float* b_val  = (const float*)d_in[14];
    const float* W_out  = (const float*)d_in[15];
    const float* b_out  = (const float*)d_in[16];
    const float* ln1_g  = (const float*)d_in[17];
    const float* ln1_b  = (const float*)d_in[18];
    const float* W_ff1  = (const float*)d_in[19];
    const float* b_ff1  = (const float*)d_in[20];
    const float* W_ff2  = (const float*)d_in[21];
    const float* b_ff2  = (const float*)d_in[22];
    const float* ln2_g  = (const float*)d_in[23];
    const float* ln2_b  = (const float*)d_in[24];

    float  *px, *ppos, *ptmp, *poa, *pbqa;
    __half *pxh, *pqh, *pvalh, *psamh, *phidh;
    __half *pWval, *pWqa, *pWout, *pWff1, *pWff2;
    cudaGetSymbolAddress((void**)&px,    g_x);
    cudaGetSymbolAddress((void**)&pxh,   g_xh);
    cudaGetSymbolAddress((void**)&ppos,  g_pos);
    cudaGetSymbolAddress((void**)&pqh,   g_qh);
    cudaGetSymbolAddress((void**)&pvalh, g_valh);
    cudaGetSymbolAddress((void**)&psamh, g_samh);
    cudaGetSymbolAddress((void**)&ptmp,  g_tmp);
    cudaGetSymbolAddress((void**)&phidh, g_hidh);
    cudaGetSymbolAddress((void**)&poa,   g_oa);
    cudaGetSymbolAddress((void**)&pWval, g_Wval);
    cudaGetSymbolAddress((void**)&pWqa,  g_Wqa);
    cudaGetSymbolAddress((void**)&pWout, g_Wout);
    cudaGetSymbolAddress((void**)&pWff1, g_Wff1);
    cudaGetSymbolAddress((void**)&pWff2, g_Wff2);
    cudaGetSymbolAddress((void**)&pbqa,  g_bqa);

    cudaFuncSetAttribute(mma_gemm<128,128>, cudaFuncAttributeMaxDynamicSharedMemorySize, SMEM128);
    cudaFuncSetAttribute(mma_gemm<64,64>,   cudaFuncAttributeMaxDynamicSharedMemorySize, SMEM64);

    // launch 1: merged weight prep
    prep_weights<<<(PREP_TOT + 255)/256, 256>>>(W_val, W_out, W_ff1, W_ff2,
                                                W_off, W_attn, b_off, b_attn);

    // launch 2: merged transposing init (all 4 levels)
    {
        dim3 blk(32, 32);
        init_all_kernel<<<dim3(331, 8, B_), blk>>>(f0, p0, f1, p1, f2, p2, f3, p3, le);
    }

    const int GM64  = (M_ + 63) / 64;    // 330
    const int GM128 = (M_ + 127) / 128;  // 165
    const int LNB   = M_ / 8;            // 2637

    for (int l = 0; l < NLAYERS_; l++) {
        // value proj -> fp16 out
        mma_gemm<64,64><<<dim3(E_/64, GM64), 256, SMEM64>>>(pxh, pWval + (size_t)l*E_*E_,
                                           b_val + l*E_, pvalh, M_, E_, E_, 2);
        // offsets + attn logits -> fp32 out
        mma_gemm<128,128><<<dim3(512/128, GM128), 256, SMEM128>>>(pqh, pWqa + (size_t)l*E_*512,
                                            pbqa + l*512, poa, M_, 512, E_, 0);

        sample_kernel<<<(M_ * NH_ * 32) / 256, 256>>>();

        // out proj: A = sampler fp16, fp32 out
        mma_gemm<64,64><<<dim3(E_/64, GM64), 256, SMEM64>>>(psamh, pWout + (size_t)l*E_*E_,
                                           b_out + l*E_, ptmp, M_, E_, E_, 0);
        ln8_kernel<<<LNB, 256>>>(px, ptmp, ln1_g + l*E_, ln1_b + l*E_, px, pxh,
                                 (const float*)0, (__half*)0);

        // ff1: relu + fp16 out
        mma_gemm<128,128><<<dim3(DF_/128, GM128), 256, SMEM128>>>(pxh, pWff1 + (size_t)l*E_*DF_,
                                            b_ff1 + l*DF_, phidh, M_, DF_, E_, 1);
        // ff2: A = hid fp16, fp32 out
        mma_gemm<64,64><<<dim3(E_/64, GM64), 256, SMEM64>>>(phidh, pWff2 + (size_t)l*DF_*E_,
                                           b_ff2 + l*E_, ptmp, M_, E_, DF_, 0);

        if (l == NLAYERS_ - 1) {
            ln8_kernel<<<LNB, 256>>>(px, ptmp, ln2_g + l*E_, ln2_b + l*E_,
                                     (float*)d_out, (__half*)0, (const float*)0, (__half*)0);
        } else {
            ln8_kernel<<<LNB, 256>>>(px, ptmp, ln2_g + l*E_, ln2_b + l*E_,
                                     px, pxh, ppos, pqh);
        }
    }
}